// round 15
// baseline (speedup 1.0000x reference)
#include <cuda_runtime.h>
#include <cuda_fp16.h>
#include <stdint.h>

typedef unsigned long long ull;

#define NROWS   65536
#define DDIM    256
#define NCODES  512
#define LDA     264            // A fp16 row stride (halfs)
#define S8S     272            // s8 row stride (bytes), conflict-free ldmatrix
#define TAU     8e-4f

// k1 smem layout (bytes)
#define A_OFF      0           // A fp16: 128*264*2 = 67584
#define PB0_OFF    67584       // Win tile0 (z phase)
#define PB1_OFF    135168      // Win tile1
#define PBUF_BYTES 67584
#define ZS8_OFF    67584       // A_s8 (reuses PB0 after z t0): 128*272 = 34816
#define MB0_OFF    102400      // M s8 tile buf A: 64*272 = 17408
#define MB1_OFF    119808      // M s8 tile buf B
#define SC_OFF     202752      // float2[512] = 4096
#define RK_OFF     206848      // 16 groups * 128 rows * 8B = 16384
#define ZSQ_OFF    223232      // 128 * f32
#define RS_OFF     223744      // 128 * f32 row scales
#define SMEM_TOTAL 224256

__device__ __align__(16) __half g_Wh[DDIM*DDIM];        // Win fp16 [e][d]
__device__ __align__(16) float  g_Mf[NCODES*DDIM];      // M = cb@Win fp32
__device__ __align__(16) char   g_Ms8[NCODES*S8S];      // M int8, padded rows
__device__ __align__(16) float2 g_schn[NCODES];         // (cscale, halfnorm)
__device__ __align__(16) float  g_Cout[NCODES*DDIM];
__device__ float g_adj_acc;
__device__ float g_zsq_acc;

// ---------------------------------------------------------------- K0
__global__ __launch_bounds__(256)
void k0_prep(const float* __restrict__ cb, const float* __restrict__ Win,
             const float* __restrict__ Wout) {
    __shared__ float cbs[4][DDIM];
    __shared__ float cmax[4];
    int b = blockIdx.x, tid = threadIdx.x;
    int ln = tid & 31, wj = tid >> 5;

    if (b < 128) {
        // M rows for 4 codes; thread = d, coalesced Win reads
        int c0 = b * 4, d = tid;
        for (int i = tid; i < 4 * DDIM; i += 256) cbs[i >> 8][i & 255] = cb[c0 * DDIM + i];
        if (tid < 4) cmax[tid] = 0.f;
        __syncthreads();
        float a0 = 0.f, a1 = 0.f, a2 = 0.f, a3 = 0.f;
        #pragma unroll 8
        for (int e = 0; e < DDIM; e++) {
            float wv = Win[e * DDIM + d];
            a0 += cbs[0][e] * wv; a1 += cbs[1][e] * wv;
            a2 += cbs[2][e] * wv; a3 += cbs[3][e] * wv;
        }
        float av[4] = { a0, a1, a2, a3 };
        #pragma unroll
        for (int j = 0; j < 4; j++) {
            g_Mf[(c0 + j) * DDIM + d] = av[j];
            float m = fabsf(av[j]);
            #pragma unroll
            for (int o = 16; o; o >>= 1) m = fmaxf(m, __shfl_xor_sync(0xffffffffu, m, o));
            if (ln == 0) atomicMax((unsigned int*)&cmax[j], __float_as_uint(m));
        }
        __syncthreads();
        #pragma unroll
        for (int j = 0; j < 4; j++) {
            float inv = 127.f / fmaxf(cmax[j], 1e-30f);
            int q = __float2int_rn(av[j] * inv);
            q = max(-127, min(127, q));
            g_Ms8[(c0 + j) * S8S + d] = (char)q;
        }
        if (wj < 4) {
            float s = 0.f;
            for (int e = ln; e < DDIM; e += 32) { float x = cbs[wj][e]; s += x * x; }
            #pragma unroll
            for (int o = 16; o; o >>= 1) s += __shfl_xor_sync(0xffffffffu, s, o);
            if (ln == 0) g_schn[c0 + wj] = make_float2(cmax[wj] * (1.f / 127.f), 0.5f * s);
        }
    } else if (b < 256) {
        // Cout for 4 codes; thread = e streams its own Wout row (L2-resident)
        int c0 = (b - 128) * 4, e = tid;
        for (int i = tid; i < 4 * DDIM; i += 256) cbs[i >> 8][i & 255] = cb[c0 * DDIM + i];
        __syncthreads();
        float a0 = 0.f, a1 = 0.f, a2 = 0.f, a3 = 0.f;
        const float4* wr = (const float4*)(Wout + (size_t)e * DDIM);
        #pragma unroll 4
        for (int d4 = 0; d4 < 64; d4++) {
            float4 wv = wr[d4];
            int d = d4 * 4;
            a0 += cbs[0][d]*wv.x + cbs[0][d+1]*wv.y + cbs[0][d+2]*wv.z + cbs[0][d+3]*wv.w;
            a1 += cbs[1][d]*wv.x + cbs[1][d+1]*wv.y + cbs[1][d+2]*wv.z + cbs[1][d+3]*wv.w;
            a2 += cbs[2][d]*wv.x + cbs[2][d+1]*wv.y + cbs[2][d+2]*wv.z + cbs[2][d+3]*wv.w;
            a3 += cbs[3][d]*wv.x + cbs[3][d+1]*wv.y + cbs[3][d+2]*wv.z + cbs[3][d+3]*wv.w;
        }
        g_Cout[(c0 + 0) * DDIM + e] = a0;
        g_Cout[(c0 + 1) * DDIM + e] = a1;
        g_Cout[(c0 + 2) * DDIM + e] = a2;
        g_Cout[(c0 + 3) * DDIM + e] = a3;
    } else {
        int e0 = (b - 256) * 8;
        for (int i = tid; i < 8 * 256; i += 256) {
            int e = e0 + (i >> 8), d = i & 255;
            g_Wh[e * 256 + d] = __float2half_rn(Win[(size_t)e * DDIM + d]);
        }
        if (b == 256 && tid == 0) { g_adj_acc = 0.f; g_zsq_acc = 0.f; }
    }
}

// ---------------------------------------------------------------- helpers
__device__ __forceinline__ void ldsm4(uint32_t& r0, uint32_t& r1, uint32_t& r2, uint32_t& r3,
                                      uint32_t addr) {
    asm volatile("ldmatrix.sync.aligned.m8n8.x4.shared.b16 {%0,%1,%2,%3},[%4];\n"
                 : "=r"(r0), "=r"(r1), "=r"(r2), "=r"(r3) : "r"(addr));
}
__device__ __forceinline__ void mma16816h(uint32_t* c, const uint32_t* a, const uint32_t* b) {
    asm volatile("mma.sync.aligned.m16n8k16.row.col.f16.f16.f16.f16 "
                 "{%0,%1},{%2,%3,%4,%5},{%6,%7},{%0,%1};\n"
                 : "+r"(c[0]), "+r"(c[1])
                 : "r"(a[0]), "r"(a[1]), "r"(a[2]), "r"(a[3]), "r"(b[0]), "r"(b[1]));
}
__device__ __forceinline__ void mma_s8(int* c, const uint32_t* a, const uint32_t* b) {
    asm volatile("mma.sync.aligned.m16n8k32.row.col.s32.s8.s8.s32 "
                 "{%0,%1,%2,%3},{%4,%5,%6,%7},{%8,%9},{%0,%1,%2,%3};\n"
                 : "+r"(c[0]), "+r"(c[1]), "+r"(c[2]), "+r"(c[3])
                 : "r"(a[0]), "r"(a[1]), "r"(a[2]), "r"(a[3]), "r"(b[0]), "r"(b[1]));
}
__device__ __forceinline__ void cp16(uint32_t dst, const void* src) {
    asm volatile("cp.async.cg.shared.global [%0],[%1],16;\n" :: "r"(dst), "l"(src));
}
__device__ __forceinline__ uint32_t fenc(float f) {
    uint32_t s = __float_as_uint(f);
    return (s & 0x80000000u) ? ~s : (s | 0x80000000u);
}
__device__ __forceinline__ float fdec(uint32_t u) {
    return (u & 0x80000000u) ? __uint_as_float(u & 0x7fffffffu) : __uint_as_float(~u);
}

// ---------------------------------------------------------------- K1
__global__ __launch_bounds__(256, 1)
void k1_main(const float* __restrict__ hidden, const unsigned char* __restrict__ mask,
             const float* __restrict__ gamma, const float* __restrict__ beta,
             float* __restrict__ dout) {
    extern __shared__ char sm[];
    float2* schn = (float2*)(sm + SC_OFF);
    ull*    rk   = (ull*)   (sm + RK_OFF);
    float*  zsq  = (float*) (sm + ZSQ_OFF);
    float*  rs   = (float*) (sm + RS_OFF);
    uint32_t sbase = (uint32_t)__cvta_generic_to_shared(sm);

    const int tid = threadIdx.x;
    const int lane = tid & 31, w = tid >> 5;
    const int wr = w >> 1, wc = w & 1;
    const int row0 = blockIdx.x << 7;

    for (int i = tid; i < 16 * 128; i += 256) rk[i] = 0ull;
    if (tid < 128) zsq[tid] = 0.f;
    for (int i = tid; i < NCODES; i += 256) schn[i] = g_schn[i];

    // A tile fp16
    for (int i = tid; i < 128 * 64; i += 256) {
        int r = i >> 6, c4 = i & 63;
        float4 h4 = *(const float4*)(hidden + (((size_t)(row0 + r)) << 8) + (c4 << 2));
        __half2 p0 = __floats2half2_rn(h4.x, h4.y);
        __half2 p1 = __floats2half2_rn(h4.z, h4.w);
        __half2* dst = (__half2*)(sm + A_OFF + ((r * LDA + (c4 << 2)) << 1));
        dst[0] = p0; dst[1] = p1;
    }
    // prefetch Win tiles (G1, G2)
    #pragma unroll
    for (int q = 0; q < 2; q++) {
        uint32_t base = sbase + (q ? PB1_OFF : PB0_OFF);
        for (int i = tid; i < 128 * 32; i += 256) {
            int r = i >> 5, ch = i & 31;
            cp16(base + ((r * LDA + (ch << 3)) << 1), g_Wh + (size_t)(q * 128 + r) * 256 + ch * 8);
        }
        asm volatile("cp.async.commit_group;\n");
    }

    // ---------------- z phase: 2 tiles, f16 acc -> ||z||^2
    for (int q = 0; q < 2; q++) {
        asm volatile("cp.async.wait_group 1;\n");
        __syncthreads();
        uint32_t acc[2][8][2];
        #pragma unroll
        for (int i = 0; i < 2; i++)
            #pragma unroll
            for (int j = 0; j < 8; j++) { acc[i][j][0] = 0u; acc[i][j][1] = 0u; }
        const uint32_t pB = sbase + (q ? PB1_OFF : PB0_OFF);
        #pragma unroll
        for (int k = 0; k < 16; k++) {
            uint32_t a[2][4];
            #pragma unroll
            for (int i = 0; i < 2; i++) {
                int arow = wr * 32 + i * 16 + (lane & 15);
                ldsm4(a[i][0], a[i][1], a[i][2], a[i][3],
                      sbase + A_OFF + ((arow * LDA + k * 16 + ((lane >> 4) << 3)) << 1));
            }
            uint32_t b[8][2];
            #pragma unroll
            for (int jj = 0; jj < 4; jj++) {
                int nrow = wc * 64 + jj * 16 + ((lane >> 4) << 3) + (lane & 7);
                int kh = (lane & 15) >> 3;
                uint32_t r0, r1, r2, r3;
                ldsm4(r0, r1, r2, r3, pB + ((nrow * LDA + k * 16 + kh * 8) << 1));
                b[jj*2][0] = r0; b[jj*2][1] = r1; b[jj*2+1][0] = r2; b[jj*2+1][1] = r3;
            }
            #pragma unroll
            for (int i = 0; i < 2; i++)
                #pragma unroll
                for (int jn = 0; jn < 8; jn++)
                    mma16816h(acc[i][jn], a[i], b[jn]);
        }
        #pragma unroll
        for (int i = 0; i < 2; i++)
            #pragma unroll
            for (int rh = 0; rh < 2; rh++) {
                int row = wr * 32 + i * 16 + rh * 8 + (lane >> 2);
                float s = 0.f;
                #pragma unroll
                for (int jn = 0; jn < 8; jn++) {
                    float2 f = __half22float2(*(__half2*)&acc[i][jn][rh]);
                    s += f.x * f.x + f.y * f.y;
                }
                s += __shfl_xor_sync(0xffffffffu, s, 1);
                s += __shfl_xor_sync(0xffffffffu, s, 2);
                if ((lane & 3) == 0) atomicAdd(&zsq[row], s);
            }
        __syncthreads();
        if (q == 0) {
            // G3: M tile0 -> MB0 (PB0 free now); then quantize A into A_s8 (PB0)
            for (int i = tid; i < 64 * 17; i += 256) {
                int c = i / 17, seg = i % 17;
                cp16(sbase + MB0_OFF + c * S8S + seg * 16, g_Ms8 + (size_t)c * S8S + seg * 16);
            }
            asm volatile("cp.async.commit_group;\n");
            // A quant: 2 threads per row
            int r = tid >> 1, hh = tid & 1;
            float m = 0.f;
            const __half2* ap = (const __half2*)(sm + A_OFF + ((r * LDA + hh * 128) << 1));
            #pragma unroll 16
            for (int j = 0; j < 64; j++) {
                float2 f = __half22float2(ap[j]);
                m = fmaxf(m, fmaxf(fabsf(f.x), fabsf(f.y)));
            }
            m = fmaxf(m, __shfl_xor_sync(0xffffffffu, m, 1));
            if (hh == 0) rs[r] = m * (1.f / 127.f);
            float inv = 127.f / fmaxf(m, 1e-30f);
            uint32_t* dst = (uint32_t*)(sm + ZS8_OFF + r * S8S + hh * 128);
            #pragma unroll 8
            for (int j = 0; j < 32; j++) {
                float2 f0 = __half22float2(ap[j * 2]);
                float2 f1 = __half22float2(ap[j * 2 + 1]);
                int q0 = max(-127, min(127, __float2int_rn(f0.x * inv)));
                int q1 = max(-127, min(127, __float2int_rn(f0.y * inv)));
                int q2 = max(-127, min(127, __float2int_rn(f1.x * inv)));
                int q3 = max(-127, min(127, __float2int_rn(f1.y * inv)));
                dst[j] = (uint32_t)(q0 & 0xFF) | ((uint32_t)(q1 & 0xFF) << 8) |
                         ((uint32_t)(q2 & 0xFF) << 16) | ((uint32_t)(q3 & 0xFF) << 24);
            }
        }
    }
    // G4: M tile1 -> MB1
    for (int i = tid; i < 64 * 17; i += 256) {
        int c = i / 17, seg = i % 17;
        cp16(sbase + MB1_OFF + c * S8S + seg * 16, g_Ms8 + (size_t)(64 + c) * S8S + seg * 16);
    }
    asm volatile("cp.async.commit_group;\n");

    // ---------------- score phase: 8 tiles of 64 codes, s8 QMMA
    for (int t = 0; t < 8; t++) {
        if (t < 7) asm volatile("cp.async.wait_group 1;\n");
        else       asm volatile("cp.async.wait_group 0;\n");
        __syncthreads();
        int acc[2][4][4];
        #pragma unroll
        for (int i = 0; i < 2; i++)
            #pragma unroll
            for (int j = 0; j < 4; j++)
                #pragma unroll
                for (int r = 0; r < 4; r++) acc[i][j][r] = 0;
        const uint32_t mB = sbase + ((t & 1) ? MB1_OFF : MB0_OFF);
        #pragma unroll
        for (int kc = 0; kc < 8; kc++) {
            uint32_t a[2][4];
            #pragma unroll
            for (int i = 0; i < 2; i++) {
                uint32_t addr = sbase + ZS8_OFF + (uint32_t)(wr * 32 + i * 16 + (lane & 15)) * S8S
                              + kc * 32 + ((lane >> 4) << 4);
                ldsm4(a[i][0], a[i][1], a[i][2], a[i][3], addr);
            }
            uint32_t b[4][2];
            #pragma unroll
            for (int p = 0; p < 2; p++) {
                uint32_t addr = mB + (uint32_t)(wc * 32 + p * 16 + (lane & 7) + ((lane >> 4) << 3)) * S8S
                              + kc * 32 + (((lane >> 3) & 1) << 4);
                uint32_t r0, r1, r2, r3;
                ldsm4(r0, r1, r2, r3, addr);
                b[p*2][0] = r0; b[p*2][1] = r1; b[p*2+1][0] = r2; b[p*2+1][1] = r3;
            }
            #pragma unroll
            for (int i = 0; i < 2; i++)
                #pragma unroll
                for (int jn = 0; jn < 4; jn++)
                    mma_s8(acc[i][jn], a[i], b[jn]);
        }
        // epilogue: group winner per (row, 32-code group)
        #pragma unroll
        for (int i = 0; i < 2; i++)
            #pragma unroll
            for (int rh = 0; rh < 2; rh++) {
                int row = wr * 32 + i * 16 + rh * 8 + (lane >> 2);
                float rsv = rs[row];
                ull best = 0ull;
                #pragma unroll
                for (int jn = 0; jn < 4; jn++)
                    #pragma unroll
                    for (int b2 = 0; b2 < 2; b2++) {
                        int code = t * 64 + wc * 32 + jn * 8 + ((lane & 3) << 1) + b2;
                        float2 sc = schn[code];
                        float adj = rsv * sc.x * (float)acc[i][jn][rh * 2 + b2] - sc.y;
                        ull key = (((ull)fenc(adj)) << 32) |
                                  (uint32_t)(0xFFFFFFFFu - (uint32_t)code);
                        if (key > best) best = key;
                    }
                ull o1 = __shfl_xor_sync(0xffffffffu, best, 1); if (o1 > best) best = o1;
                ull o2 = __shfl_xor_sync(0xffffffffu, best, 2); if (o2 > best) best = o2;
                if ((lane & 3) == 0) atomicMax(&rk[(t * 2 + wc) * 128 + row], best);
            }
        __syncthreads();
        if (t < 6) {
            uint32_t dstb = sbase + ((t & 1) ? MB1_OFF : MB0_OFF);
            const char* src = g_Ms8 + (size_t)(t + 2) * 64 * S8S;
            for (int i = tid; i < 64 * 17; i += 256) {
                int c = i / 17, seg = i % 17;
                cp16(dstb + c * S8S + seg * 16, src + (size_t)c * S8S + seg * 16);
            }
            asm volatile("cp.async.commit_group;\n");
        }
    }

    // ---------------- final: select(+refine), gather Cout, LN, loss
    float adjacc = 0.f, zacc = 0.f;
    for (int rr = 0; rr < 16; rr++) {
        int row = w * 16 + rr;
        int grow = row0 + row;
        ull key = (lane < 16) ? rk[lane * 128 + row] : 0ull;
        ull bk = key;
        #pragma unroll
        for (int o = 16; o; o >>= 1) { ull x = __shfl_xor_sync(0xffffffffu, bk, o); if (x > bk) bk = x; }
        ull s2 = (key == bk) ? 0ull : key;
        #pragma unroll
        for (int o = 16; o; o >>= 1) { ull x = __shfl_xor_sync(0xffffffffu, s2, o); if (x > s2) s2 = x; }
        float a1 = fdec((uint32_t)(bk >> 32));
        float a2 = fdec((uint32_t)(s2 >> 32));
        int idx_fin = (int)(0xFFFFFFFFu - (uint32_t)(bk & 0xFFFFFFFFull));
        float adj_fin = a1;

        const float4* hp = (const float4*)(hidden + (((size_t)grow) << 8));
        float4 h1 = hp[lane], h2 = hp[lane + 32];

        if (a1 - a2 < TAU) {   // refine near-ties exactly (fp32 h . Mf)
            float bestA = -1e30f; int bidx = 0x7FFFFFFF;
            #pragma unroll 1
            for (int c = 0; c < 16; c++) {
                ull ck = __shfl_sync(0xffffffffu, key, c);
                float ca = fdec((uint32_t)(ck >> 32));
                if (ca >= a1 - TAU) {
                    int ci = (int)(0xFFFFFFFFu - (uint32_t)(ck & 0xFFFFFFFFull));
                    const float4* mp = (const float4*)(g_Mf + (size_t)ci * DDIM);
                    float4 m1 = mp[lane], m2 = mp[lane + 32];
                    float d = h1.x*m1.x + h1.y*m1.y + h1.z*m1.z + h1.w*m1.w
                            + h2.x*m2.x + h2.y*m2.y + h2.z*m2.z + h2.w*m2.w;
                    #pragma unroll
                    for (int o = 16; o; o >>= 1) d += __shfl_xor_sync(0xffffffffu, d, o);
                    float adjE = d - schn[ci].y;
                    if (adjE > bestA || (adjE == bestA && ci < bidx)) { bestA = adjE; bidx = ci; }
                }
            }
            idx_fin = bidx; adj_fin = bestA;
        }
        if (lane == 0) { adjacc += adj_fin; zacc += zsq[row]; }

        float m = mask[grow] ? 1.0f : 0.0f;
        const float4* op = (const float4*)(g_Cout + (((size_t)idx_fin) << 8));
        float4 o1 = op[lane], o2 = op[lane + 32];
        float v[8] = { h1.x + m * o1.x, h1.y + m * o1.y, h1.z + m * o1.z, h1.w + m * o1.w,
                       h2.x + m * o2.x, h2.y + m * o2.y, h2.z + m * o2.z, h2.w + m * o2.w };
        float s = 0.f;
        #pragma unroll
        for (int j = 0; j < 8; j++) s += v[j];
        #pragma unroll
        for (int o = 16; o; o >>= 1) s += __shfl_xor_sync(0xffffffffu, s, o);
        float mu = s * (1.f / 256.f);
        float qv = 0.f;
        #pragma unroll
        for (int j = 0; j < 8; j++) { float d = v[j] - mu; qv += d * d; }
        #pragma unroll
        for (int o = 16; o; o >>= 1) qv += __shfl_xor_sync(0xffffffffu, qv, o);
        float rstd = rsqrtf(qv * (1.f / 256.f) + 1e-5f);

        const float4* gp = (const float4*)gamma;
        const float4* bp = (const float4*)beta;
        float4 g1 = gp[lane], g2 = gp[lane + 32];
        float4 b1 = bp[lane], b2 = bp[lane + 32];
        float4 oA, oB;
        oA.x = (v[0]-mu)*rstd*g1.x + b1.x;  oA.y = (v[1]-mu)*rstd*g1.y + b1.y;
        oA.z = (v[2]-mu)*rstd*g1.z + b1.z;  oA.w = (v[3]-mu)*rstd*g1.w + b1.w;
        oB.x = (v[4]-mu)*rstd*g2.x + b2.x;  oB.y = (v[5]-mu)*rstd*g2.y + b2.y;
        oB.z = (v[6]-mu)*rstd*g2.z + b2.z;  oB.w = (v[7]-mu)*rstd*g2.w + b2.w;
        float4* dp = (float4*)(dout + (((size_t)grow) << 8));
        dp[lane] = oA; dp[lane + 32] = oB;
    }
    if (lane == 0) { atomicAdd(&g_adj_acc, adjacc); atomicAdd(&g_zsq_acc, zacc); }
}

// ---------------------------------------------------------------- K2
__global__ void k2_loss(float* dout, int outsize) {
    float num = g_zsq_acc - 2.f * g_adj_acc;
    float loss = 1.25f * num / (float)((size_t)NROWS * DDIM);
    for (int i = NROWS * DDIM + (int)threadIdx.x; i < outsize; i += (int)blockDim.x)
        dout[i] = loss;
}

// ---------------------------------------------------------------- launch
extern "C" void kernel_launch(void* const* d_in, const int* in_sizes, int n_in,
                              void* d_out, int out_size) {
    const float*         hidden = (const float*)d_in[0];
    const unsigned char* mask   = (const unsigned char*)d_in[1];
    const float*         cb     = (const float*)d_in[2];
    const float*         Win    = (const float*)d_in[3];
    const float*         Wout   = (const float*)d_in[4];
    const float*         gamma  = (const float*)d_in[5];
    const float*         beta   = (const float*)d_in[6];
    float* out = (float*)d_out;

    cudaFuncSetAttribute(k1_main, cudaFuncAttributeMaxDynamicSharedMemorySize, SMEM_TOTAL);

    k0_prep<<<288, 256>>>(cb, Win, Wout);
    k1_main<<<NROWS / 128, 256, SMEM_TOTAL>>>(hidden, mask, gamma, beta, out);
    k2_loss<<<1, 32>>>(out, out_size);
}

// round 17
// speedup vs baseline: 1.8394x; 1.8394x over previous
#include <cuda_runtime.h>
#include <cuda_fp16.h>
#include <stdint.h>

typedef unsigned long long ull;

#define NROWS   65536
#define DDIM    256
#define NCODES  512
#define PCOLS   768
#define TM      128
#define TN      128
#define NTILES  6            // tiles 0..3 scores, 4..5 z
#define LDA     264

#define A_OFF      0
#define A_BYTES    (TM*LDA*2)
#define P_OFF      A_BYTES
#define PBUF_BYTES (TN*LDA*2)
#define HN_OFF     (A_BYTES + 2*PBUF_BYTES)
#define RK_OFF     (HN_OFF + NCODES*4)
#define ZQ_OFF     (RK_OFF + TM*8)
#define SMEM_TOTAL (ZQ_OFF + TM*4)

__device__ __align__(16) __half g_P[PCOLS*DDIM];
__device__ __align__(16) float g_Cout[NCODES*DDIM];
__device__ float g_halfnorm[NCODES];
__device__ float g_adj_acc;
__device__ float g_zsq_acc;

// ---------------------------------------------------------------- K0 (544 blocks, 2 codes each)
__global__ __launch_bounds__(256)
void k0_prep(const float* __restrict__ cb, const float* __restrict__ Win,
             const float* __restrict__ Wout) {
    __shared__ float cbs[2][DDIM];
    int b = blockIdx.x, tid = threadIdx.x;
    int ln = tid & 31, wj = tid >> 5;

    if (b < 256) {
        // M = cb @ Win for 2 codes; thread = d, coalesced Win reads
        int c0 = b * 2, d = tid;
        for (int i = tid; i < 2 * DDIM; i += 256) cbs[i >> 8][i & 255] = cb[c0 * DDIM + i];
        __syncthreads();
        float a0 = 0.f, a1 = 0.f;
        #pragma unroll 16
        for (int e = 0; e < DDIM; e++) {
            float wv = Win[e * DDIM + d];
            a0 += cbs[0][e] * wv;
            a1 += cbs[1][e] * wv;
        }
        g_P[(c0 + 0) * DDIM + d] = __float2half_rn(a0);
        g_P[(c0 + 1) * DDIM + d] = __float2half_rn(a1);
        if (wj < 2) {
            float s = 0.f;
            for (int e = ln; e < DDIM; e += 32) { float x = cbs[wj][e]; s += x * x; }
            #pragma unroll
            for (int o = 16; o; o >>= 1) s += __shfl_xor_sync(0xffffffffu, s, o);
            if (ln == 0) g_halfnorm[c0 + wj] = 0.5f * s;
        }
    } else if (b < 512) {
        // Cout for 2 codes; thread = e streams its Wout row
        int c0 = (b - 256) * 2, e = tid;
        for (int i = tid; i < 2 * DDIM; i += 256) cbs[i >> 8][i & 255] = cb[c0 * DDIM + i];
        __syncthreads();
        float a0 = 0.f, a1 = 0.f;
        const float4* wr = (const float4*)(Wout + (size_t)e * DDIM);
        #pragma unroll 8
        for (int d4 = 0; d4 < 64; d4++) {
            float4 wv = wr[d4];
            int d = d4 * 4;
            a0 += cbs[0][d]*wv.x + cbs[0][d+1]*wv.y + cbs[0][d+2]*wv.z + cbs[0][d+3]*wv.w;
            a1 += cbs[1][d]*wv.x + cbs[1][d+1]*wv.y + cbs[1][d+2]*wv.z + cbs[1][d+3]*wv.w;
        }
        g_Cout[(c0 + 0) * DDIM + e] = a0;
        g_Cout[(c0 + 1) * DDIM + e] = a1;
    } else {
        // blocks 512..543: Win rows -> P rows 512..767 (fp16)
        int e0 = (b - 512) * 8;
        for (int i = tid; i < 8 * 256; i += 256) {
            int e = e0 + (i >> 8), d = i & 255;
            g_P[(NCODES + e) * DDIM + d] = __float2half_rn(Win[(size_t)e * DDIM + d]);
        }
        if (b == 512 && tid == 0) { g_adj_acc = 0.f; g_zsq_acc = 0.f; }
    }
}

// ---------------------------------------------------------------- helpers
__device__ __forceinline__ void ldsm4(uint32_t& r0, uint32_t& r1, uint32_t& r2, uint32_t& r3,
                                      uint32_t addr) {
    asm volatile("ldmatrix.sync.aligned.m8n8.x4.shared.b16 {%0,%1,%2,%3},[%4];\n"
                 : "=r"(r0), "=r"(r1), "=r"(r2), "=r"(r3) : "r"(addr));
}
__device__ __forceinline__ void mma16816h(uint32_t* c, const uint32_t* a, const uint32_t* b) {
    asm volatile("mma.sync.aligned.m16n8k16.row.col.f16.f16.f16.f16 "
                 "{%0,%1},{%2,%3,%4,%5},{%6,%7},{%0,%1};\n"
                 : "+r"(c[0]), "+r"(c[1])
                 : "r"(a[0]), "r"(a[1]), "r"(a[2]), "r"(a[3]), "r"(b[0]), "r"(b[1]));
}
__device__ __forceinline__ void cp16(uint32_t dst, const void* src) {
    asm volatile("cp.async.cg.shared.global [%0],[%1],16;\n" :: "r"(dst), "l"(src));
}
__device__ __forceinline__ uint32_t fenc(float f) {
    uint32_t s = __float_as_uint(f);
    return (s & 0x80000000u) ? ~s : (s | 0x80000000u);
}

// ---------------------------------------------------------------- K1 (R8 config, unchanged)
__global__ __launch_bounds__(256, 1)
void k1_main(const float* __restrict__ hidden, const unsigned char* __restrict__ mask,
             const float* __restrict__ gamma, const float* __restrict__ beta,
             float* __restrict__ dout) {
    extern __shared__ char sm[];
    float* hn     = (float*)(sm + HN_OFF);
    ull*   rowkey = (ull*)  (sm + RK_OFF);
    float* zsq    = (float*)(sm + ZQ_OFF);
    uint32_t sbase = (uint32_t)__cvta_generic_to_shared(sm);

    const int tid = threadIdx.x;
    const int lane = tid & 31, w = tid >> 5;
    const int wr = w >> 1, wc = w & 1;
    const int row0 = blockIdx.x << 7;

    if (tid < TM) { rowkey[tid] = 0ull; zsq[tid] = 0.f; }
    for (int i = tid; i < NCODES; i += 256) hn[i] = g_halfnorm[i];

    for (int i = tid; i < TM * 64; i += 256) {
        int r = i >> 6, c4 = i & 63;
        float4 h4 = *(const float4*)(hidden + (((size_t)(row0 + r)) << 8) + (c4 << 2));
        __half2 p0 = __floats2half2_rn(h4.x, h4.y);
        __half2 p1 = __floats2half2_rn(h4.z, h4.w);
        __half2* dst = (__half2*)(sm + ((r * LDA + (c4 << 2)) << 1));
        dst[0] = p0; dst[1] = p1;
    }
    for (int i = tid; i < TN * 32; i += 256) {
        int c = i >> 5, ch = i & 31;
        cp16(sbase + P_OFF + ((c * LDA + (ch << 3)) << 1), g_P + (((size_t)c) << 8) + (ch << 3));
    }
    asm volatile("cp.async.commit_group;\n");

    for (int t = 0; t < NTILES; t++) {
        if (t < NTILES - 1) {
            int buf = (t + 1) & 1;
            for (int i = tid; i < TN * 32; i += 256) {
                int c = i >> 5, ch = i & 31;
                cp16(sbase + P_OFF + buf * PBUF_BYTES + ((c * LDA + (ch << 3)) << 1),
                     g_P + (((size_t)((t + 1) * TN + c)) << 8) + (ch << 3));
            }
            asm volatile("cp.async.commit_group;\n");
            asm volatile("cp.async.wait_group 1;\n");
        } else {
            asm volatile("cp.async.wait_group 0;\n");
        }
        __syncthreads();

        uint32_t acc[2][8][2];
        #pragma unroll
        for (int i = 0; i < 2; i++)
            #pragma unroll
            for (int j = 0; j < 8; j++) { acc[i][j][0] = 0u; acc[i][j][1] = 0u; }

        const uint32_t pB = sbase + P_OFF + (t & 1) * PBUF_BYTES;
        #pragma unroll
        for (int k = 0; k < 16; k++) {
            uint32_t a[2][4];
            #pragma unroll
            for (int i = 0; i < 2; i++) {
                int arow = wr * 32 + i * 16 + (lane & 15);
                ldsm4(a[i][0], a[i][1], a[i][2], a[i][3],
                      sbase + ((arow * LDA + k * 16 + ((lane >> 4) << 3)) << 1));
            }
            uint32_t b[8][2];
            #pragma unroll
            for (int jj = 0; jj < 4; jj++) {
                int nrow = wc * 64 + jj * 16 + ((lane >> 4) << 3) + (lane & 7);
                int kh = (lane & 15) >> 3;
                uint32_t r0, r1, r2, r3;
                ldsm4(r0, r1, r2, r3, pB + ((nrow * LDA + k * 16 + kh * 8) << 1));
                b[jj * 2][0] = r0; b[jj * 2][1] = r1;
                b[jj * 2 + 1][0] = r2; b[jj * 2 + 1][1] = r3;
            }
            #pragma unroll
            for (int i = 0; i < 2; i++)
                #pragma unroll
                for (int jn = 0; jn < 8; jn++)
                    mma16816h(acc[i][jn], a[i], b[jn]);
        }

        if (t < 4) {
            #pragma unroll
            for (int i = 0; i < 2; i++)
                #pragma unroll
                for (int rh = 0; rh < 2; rh++) {
                    int rrow = wr * 32 + i * 16 + rh * 8 + (lane >> 2);
                    ull best = 0ull;
                    #pragma unroll
                    for (int jn = 0; jn < 8; jn++) {
                        float2 f = __half22float2(*(__half2*)&acc[i][jn][rh]);
                        int code = t * TN + wc * 64 + jn * 8 + ((lane & 3) << 1);
                        float adj0 = f.x - hn[code];
                        float adj1 = f.y - hn[code + 1];
                        ull k0v = (((ull)fenc(adj0)) << 32) |
                                  (uint32_t)(0xFFFFFFFFu - (uint32_t)code);
                        ull k1v = (((ull)fenc(adj1)) << 32) |
                                  (uint32_t)(0xFFFFFFFFu - (uint32_t)(code + 1));
                        if (k0v > best) best = k0v;
                        if (k1v > best) best = k1v;
                    }
                    ull o1 = __shfl_xor_sync(0xffffffffu, best, 1); best = (o1 > best) ? o1 : best;
                    ull o2 = __shfl_xor_sync(0xffffffffu, best, 2); best = (o2 > best) ? o2 : best;
                    if ((lane & 3) == 0) atomicMax(&rowkey[rrow], best);
                }
        } else {
            #pragma unroll
            for (int i = 0; i < 2; i++)
                #pragma unroll
                for (int rh = 0; rh < 2; rh++) {
                    int rrow = wr * 32 + i * 16 + rh * 8 + (lane >> 2);
                    float s = 0.f;
                    #pragma unroll
                    for (int jn = 0; jn < 8; jn++) {
                        float2 f = __half22float2(*(__half2*)&acc[i][jn][rh]);
                        s += f.x * f.x + f.y * f.y;
                    }
                    s += __shfl_xor_sync(0xffffffffu, s, 1);
                    s += __shfl_xor_sync(0xffffffffu, s, 2);
                    if ((lane & 3) == 0) atomicAdd(&zsq[rrow], s);
                }
        }
        __syncthreads();
    }

    float adjacc = 0.f, zacc = 0.f;
    #pragma unroll
    for (int rr = 0; rr < 16; rr++) {
        int row = (w << 4) + rr;
        int grow = row0 + row;
        ull key = rowkey[row];
        uint32_t ua = (uint32_t)(key >> 32);
        float adj = (ua & 0x80000000u) ? __uint_as_float(ua & 0x7fffffffu)
                                       : __uint_as_float(~ua);
        int idx = (int)(0xFFFFFFFFu - (uint32_t)(key & 0xFFFFFFFFull));
        if (lane == 0) { adjacc += adj; zacc += zsq[row]; }

        float m = mask[grow] ? 1.0f : 0.0f;
        const float4* hp = (const float4*)(hidden + (((size_t)grow) << 8));
        const float4* op = (const float4*)(g_Cout + (((size_t)idx) << 8));
        float4 h1 = hp[lane], h2 = hp[lane + 32];
        float4 o1 = op[lane], o2 = op[lane + 32];
        float v[8] = { h1.x + m * o1.x, h1.y + m * o1.y, h1.z + m * o1.z, h1.w + m * o1.w,
                       h2.x + m * o2.x, h2.y + m * o2.y, h2.z + m * o2.z, h2.w + m * o2.w };
        float s = 0.f;
        #pragma unroll
        for (int j = 0; j < 8; j++) s += v[j];
        #pragma unroll
        for (int o = 16; o; o >>= 1) s += __shfl_xor_sync(0xffffffffu, s, o);
        float mu = s * (1.f / 256.f);
        float q = 0.f;
        #pragma unroll
        for (int j = 0; j < 8; j++) { float d = v[j] - mu; q += d * d; }
        #pragma unroll
        for (int o = 16; o; o >>= 1) q += __shfl_xor_sync(0xffffffffu, q, o);
        float rstd = rsqrtf(q * (1.f / 256.f) + 1e-5f);

        const float4* gp = (const float4*)gamma;
        const float4* bp = (const float4*)beta;
        float4 g1 = gp[lane], g2 = gp[lane + 32];
        float4 b1 = bp[lane], b2 = bp[lane + 32];
        float4 oA, oB;
        oA.x = (v[0]-mu)*rstd*g1.x + b1.x;  oA.y = (v[1]-mu)*rstd*g1.y + b1.y;
        oA.z = (v[2]-mu)*rstd*g1.z + b1.z;  oA.w = (v[3]-mu)*rstd*g1.w + b1.w;
        oB.x = (v[4]-mu)*rstd*g2.x + b2.x;  oB.y = (v[5]-mu)*rstd*g2.y + b2.y;
        oB.z = (v[6]-mu)*rstd*g2.z + b2.z;  oB.w = (v[7]-mu)*rstd*g2.w + b2.w;
        float4* dp = (float4*)(dout + (((size_t)grow) << 8));
        dp[lane] = oA; dp[lane + 32] = oB;
    }
    if (lane == 0) { atomicAdd(&g_adj_acc, adjacc); atomicAdd(&g_zsq_acc, zacc); }
}

// ---------------------------------------------------------------- K2
__global__ void k2_loss(float* dout, int outsize) {
    float num = g_zsq_acc - 2.f * g_adj_acc;
    float loss = 1.25f * num / (float)((size_t)NROWS * DDIM);
    for (int i = NROWS * DDIM + (int)threadIdx.x; i < outsize; i += (int)blockDim.x)
        dout[i] = loss;
}

// ---------------------------------------------------------------- launch
extern "C" void kernel_launch(void* const* d_in, const int* in_sizes, int n_in,
                              void* d_out, int out_size) {
    const float*         hidden = (const float*)d_in[0];
    const unsigned char* mask   = (const unsigned char*)d_in[1];
    const float*         cb     = (const float*)d_in[2];
    const float*         Win    = (const float*)d_in[3];
    const float*         Wout   = (const float*)d_in[4];
    const float*         gamma  = (const float*)d_in[5];
    const float*         beta   = (const float*)d_in[6];
    float* out = (float*)d_out;

    cudaFuncSetAttribute(k1_main, cudaFuncAttributeMaxDynamicSharedMemorySize, SMEM_TOTAL);

    k0_prep<<<544, 256>>>(cb, Win, Wout);
    k1_main<<<NROWS / TM, 256, SMEM_TOTAL>>>(hidden, mask, gamma, beta, out);
    k2_loss<<<1, 32>>>(out, out_size);
}